// round 6
// baseline (speedup 1.0000x reference)
#include <cuda_runtime.h>
#include <cuda_fp16.h>

#define NN 100000
#define NE 3200000
#define ET (NE + NN)
#define SMAX 128
#define NW 8            // warps per edge-kernel block
#define SCAN_BLK 256
#define NB ((NN + SCAN_BLK - 1) / SCAN_BLK)   // 391

// ---------------- scratch (device globals; no allocs allowed) ----------------
__device__ __align__(128) int     g_cnt[NN];      // counts (init 1 for self-loop), then cursor
__device__ __align__(128) int     g_off[NN + 1];  // CSR offsets by dst
__device__ __align__(128) int     g_csr[ET];      // src node id per CSR slot
__device__ __align__(128) int     g_blk[NB];      // per-block sums -> inclusive prefixes
__device__ __align__(128) __half2 g_hh[NN * 16];  // node features fp16 (stride = CH/2 of layer)
__device__ __align__(128) float   g_o[NN * 32];   // aggregated out (fp32)
__device__ __align__(128) float   g_als[NN * 2];  // per-node src-attention scalar [n][h]
__device__ __align__(128) float   g_ald[NN * 2];  // per-node dst-attention scalar [n][h]

// ---------------- CSR build ----------------
__global__ void k_zero() {
    int i = blockIdx.x * blockDim.x + threadIdx.x;
    if (i < NN) g_cnt[i] = 1;          // self-loop pre-counted
}

__global__ void k_count(const int4* __restrict__ dst4) {
    int e = blockIdx.x * blockDim.x + threadIdx.x;
    if (e >= NE / 4) return;
    int4 d = dst4[e];
    atomicAdd(&g_cnt[d.x], 1);
    atomicAdd(&g_cnt[d.y], 1);
    atomicAdd(&g_cnt[d.z], 1);
    atomicAdd(&g_cnt[d.w], 1);
}

// per-block sums of g_cnt
__global__ void k_blksum() {
    __shared__ int sm[SCAN_BLK];
    int n = blockIdx.x * SCAN_BLK + threadIdx.x;
    sm[threadIdx.x] = (n < NN) ? g_cnt[n] : 0;
    __syncthreads();
#pragma unroll
    for (int o = SCAN_BLK / 2; o > 0; o >>= 1) {
        if (threadIdx.x < o) sm[threadIdx.x] += sm[threadIdx.x + o];
        __syncthreads();
    }
    if (threadIdx.x == 0) g_blk[blockIdx.x] = sm[0];
}

// single small block: inclusive scan over the NB block sums
__global__ void k_blkscan() {
    __shared__ int sm[512];
    int tid = threadIdx.x;
    sm[tid] = (tid < NB) ? g_blk[tid] : 0;
    __syncthreads();
    for (int d = 1; d < 512; d <<= 1) {
        int t = (tid >= d) ? sm[tid - d] : 0;
        __syncthreads();
        sm[tid] += t;
        __syncthreads();
    }
    if (tid < NB) g_blk[tid] = sm[tid];   // inclusive prefix
}

// per-block: local scan of 256 counts, add block prefix, emit offsets + self-loop + cursor
__global__ void k_offsets() {
    __shared__ int sm[SCAN_BLK];
    int b = blockIdx.x;
    int n = b * SCAN_BLK + threadIdx.x;
    int c = (n < NN) ? g_cnt[n] : 0;
    sm[threadIdx.x] = c;
    __syncthreads();
    for (int d = 1; d < SCAN_BLK; d <<= 1) {
        int t = (threadIdx.x >= d) ? sm[threadIdx.x - d] : 0;
        __syncthreads();
        sm[threadIdx.x] += t;
        __syncthreads();
    }
    int blocksum = sm[SCAN_BLK - 1];
    int base = g_blk[b] - blocksum;               // exclusive block prefix
    int run = base + sm[threadIdx.x] - c;         // exclusive node prefix
    if (n < NN) {
        g_off[n] = run;
        g_csr[run] = n;          // self-loop first
        g_cnt[n] = run + 1;      // scatter cursor after self-loop
        if (n == NN - 1) g_off[NN] = run + c;
    }
}

__global__ void k_scatter(const int4* __restrict__ src4, const int4* __restrict__ dst4) {
    int e = blockIdx.x * blockDim.x + threadIdx.x;
    if (e >= NE / 4) return;
    int4 s = src4[e];
    int4 d = dst4[e];
    g_csr[atomicAdd(&g_cnt[d.x], 1)] = s.x;
    g_csr[atomicAdd(&g_cnt[d.y], 1)] = s.y;
    g_csr[atomicAdd(&g_cnt[d.z], 1)] = s.z;
    g_csr[atomicAdd(&g_cnt[d.w], 1)] = s.w;
}

// ---------------- layer 1 node transform ----------------
__global__ void k_node1(const float* __restrict__ x, const float* __restrict__ W,
                        const float* __restrict__ as_, const float* __restrict__ ad_) {
    int n = blockIdx.x * blockDim.x + threadIdx.x;
    if (n >= NN) return;
    float x0 = x[n * 3 + 0], x1 = x[n * 3 + 1], x2 = x[n * 3 + 2];
    float als0 = 0.f, als1 = 0.f, ald0 = 0.f, ald1 = 0.f;
    float hv[32];
#pragma unroll
    for (int c = 0; c < 32; c++) {
        float h = fmaf(x0, __ldg(&W[c]), fmaf(x1, __ldg(&W[32 + c]), x2 * __ldg(&W[64 + c])));
        hv[c] = h;
        float vs = h * __ldg(&as_[c]), vd = h * __ldg(&ad_[c]);
        if (c < 16) { als0 += vs; ald0 += vd; }
        else        { als1 += vs; ald1 += vd; }
    }
#pragma unroll
    for (int j = 0; j < 16; j++)
        g_hh[n * 16 + j] = __floats2half2_rn(hv[2 * j], hv[2 * j + 1]);
    g_als[n * 2 + 0] = als0; g_als[n * 2 + 1] = als1;
    g_ald[n * 2 + 0] = ald0; g_ald[n * 2 + 1] = ald1;
}

__device__ __forceinline__ float lrelu(float v) { return v > 0.f ? v : 0.2f * v; }

// ---------------- edge aggregation, H=2 CH=32: one warp per dst ----------------
__global__ void __launch_bounds__(256) k_edge2() {
    __shared__ int   s_s[NW][SMAX];
    __shared__ float s_a[NW][SMAX * 2];   // [jj][h] interleaved
    int widx = threadIdx.x >> 5;
    int lane = threadIdx.x & 31;
    int w = blockIdx.x * NW + widx;       // NN % NW == 0

    int start = g_off[w];
    int deg   = g_off[w + 1] - start;
    float2 aldv = ((const float2*)g_ald)[w];

    // phase A: exp(logit) per edge (fp32), denominator, cache (src, e0, e1)
    float ss0 = 0.f, ss1 = 0.f;
    for (int jj = lane; jj < deg; jj += 32) {
        int s = g_csr[start + jj];
        float2 av = ((const float2*)g_als)[s];
        float e0 = __expf(lrelu(av.x + aldv.x));
        float e1 = __expf(lrelu(av.y + aldv.y));
        ss0 += e0; ss1 += e1;
        if (jj < SMAX) {
            s_s[widx][jj] = s;
            ((float2*)s_a[widx])[jj] = make_float2(e0, e1);
        }
    }
#pragma unroll
    for (int o = 16; o > 0; o >>= 1) {
        ss0 += __shfl_xor_sync(0xffffffffu, ss0, o);
        ss1 += __shfl_xor_sync(0xffffffffu, ss1, o);
    }
    __syncwarp();

    // phase C: two edges per warp step; lane = (edge group, half2 channel pair)
    int c2 = lane & 15;        // half2 index -> channels 2c2, 2c2+1
    int eg = lane >> 4;        // edge group 0/1
    int hsel = c2 >> 3;        // head of this channel pair
    float accx = 0.f, accy = 0.f;
    int lim = min(deg, SMAX);
    int jj = 0;
    for (; jj + 8 <= lim; jj += 8) {
#pragma unroll
        for (int u = 0; u < 4; u++) {
            int e = jj + 2 * u + eg;
            int s = s_s[widx][e];
            float a = s_a[widx][e * 2 + hsel];
            float2 f = __half22float2(g_hh[s * 16 + c2]);
            accx = fmaf(a, f.x, accx);
            accy = fmaf(a, f.y, accy);
        }
    }
#pragma unroll 1
    for (int e = jj + eg; e < lim; e += 2) {
        int s = s_s[widx][e];
        float a = s_a[widx][e * 2 + hsel];
        float2 f = __half22float2(g_hh[s * 16 + c2]);
        accx = fmaf(a, f.x, accx);
        accy = fmaf(a, f.y, accy);
    }
#pragma unroll 1
    for (int e = lim + eg; e < deg; e += 2) {   // overflow fallback (deg > SMAX; ~never)
        int s = g_csr[start + e];
        float2 av = ((const float2*)g_als)[s];
        float v = (hsel ? av.y : av.x) + (hsel ? aldv.y : aldv.x);
        float a = __expf(lrelu(v));
        float2 f = __half22float2(g_hh[s * 16 + c2]);
        accx = fmaf(a, f.x, accx);
        accy = fmaf(a, f.y, accy);
    }
    // combine the two edge groups
    accx += __shfl_xor_sync(0xffffffffu, accx, 16);
    accy += __shfl_xor_sync(0xffffffffu, accy, 16);
    float inv = 1.f / ((hsel ? ss1 : ss0) + 1e-16f);
    if (eg == 0)
        ((float2*)g_o)[w * 16 + c2] = make_float2(accx * inv, accy * inv);
}

// ---------------- layer 3 edges (H=1, CH=8) fused with output head ----------------
__global__ void __launch_bounds__(256) k_edge1_final(
        const float* __restrict__ b3, const float* __restrict__ Wo,
        const float* __restrict__ bo, float* __restrict__ out) {
    __shared__ int   s_s[NW][SMAX];
    __shared__ float s_a[NW][SMAX];
    int widx = threadIdx.x >> 5;
    int lane = threadIdx.x & 31;
    int w = blockIdx.x * NW + widx;

    int start = g_off[w];
    int deg   = g_off[w + 1] - start;
    float aldv = g_ald[w];

    float ss = 0.f;
    for (int jj = lane; jj < deg; jj += 32) {
        int s = g_csr[start + jj];
        float e = __expf(lrelu(g_als[s] + aldv));
        ss += e;
        if (jj < SMAX) { s_s[widx][jj] = s; s_a[widx][jj] = e; }
    }
#pragma unroll
    for (int o = 16; o > 0; o >>= 1) ss += __shfl_xor_sync(0xffffffffu, ss, o);
    __syncwarp();
    float inv = 1.f / (ss + 1e-16f);

    // phase C: 8 edge groups x 4 half2 channel pairs
    int eg = lane >> 2, c2 = lane & 3;
    float accx = 0.f, accy = 0.f;
    int lim = min(deg, SMAX);
    for (int e = eg; e < lim; e += 8) {
        float a = s_a[widx][e];
        float2 f = __half22float2(g_hh[s_s[widx][e] * 4 + c2]);
        accx = fmaf(a, f.x, accx);
        accy = fmaf(a, f.y, accy);
    }
#pragma unroll 1
    for (int e = lim + eg; e < deg; e += 8) {   // overflow fallback
        int s = g_csr[start + e];
        float a = __expf(lrelu(g_als[s] + aldv));
        float2 f = __half22float2(g_hh[s * 4 + c2]);
        accx = fmaf(a, f.x, accx);
        accy = fmaf(a, f.y, accy);
    }
    // reduce over the 8 edge groups (bits 2..4)
#pragma unroll
    for (int o = 4; o <= 16; o <<= 1) {
        accx += __shfl_xor_sync(0xffffffffu, accx, o);
        accy += __shfl_xor_sync(0xffffffffu, accy, o);
    }

    // fused head: y = elu(out3 + b3) @ Wo + bo   (channels 2c2, 2c2+1)
    float z0 = accx * inv + __ldg(&b3[2 * c2]);
    float z1 = accy * inv + __ldg(&b3[2 * c2 + 1]);
    z0 = z0 > 0.f ? z0 : expm1f(z0);
    z1 = z1 > 0.f ? z1 : expm1f(z1);
    float p = fmaf(z0, __ldg(&Wo[2 * c2]), z1 * __ldg(&Wo[2 * c2 + 1]));
    p += __shfl_xor_sync(0xffffffffu, p, 1);
    p += __shfl_xor_sync(0xffffffffu, p, 2);
    if (lane == 0) out[w] = p + __ldg(&bo[0]);
}

// ---------------- mid node transform ----------------
template <int CIN, int COUT, int H>
__global__ void k_mid(const float* __restrict__ b, const float* __restrict__ W,
                      const float* __restrict__ as_, const float* __restrict__ ad_) {
    __shared__ float sW[CIN * COUT];
    __shared__ float sb[CIN];
    __shared__ float sas[COUT], sad[COUT];
    for (int i = threadIdx.x; i < CIN * COUT; i += blockDim.x) sW[i] = W[i];
    for (int i = threadIdx.x; i < CIN; i += blockDim.x) sb[i] = b[i];
    for (int i = threadIdx.x; i < COUT; i += blockDim.x) { sas[i] = as_[i]; sad[i] = ad_[i]; }
    __syncthreads();

    int n = blockIdx.x * blockDim.x + threadIdx.x;
    if (n >= NN) return;
    float z[CIN];
#pragma unroll
    for (int i = 0; i < CIN; i++) {
        float v = g_o[n * CIN + i] + sb[i];
        z[i] = v > 0.f ? v : expm1f(v);              // elu
    }
    const int C = COUT / H;
    float als[H], ald[H];
#pragma unroll
    for (int h = 0; h < H; h++) { als[h] = 0.f; ald[h] = 0.f; }
    float hv[COUT];
#pragma unroll
    for (int c = 0; c < COUT; c++) {
        float acc = 0.f;
#pragma unroll
        for (int i = 0; i < CIN; i++) acc = fmaf(z[i], sW[i * COUT + c], acc);
        hv[c] = acc;
        int h = c / C;
        als[h] = fmaf(acc, sas[c], als[h]);
        ald[h] = fmaf(acc, sad[c], ald[h]);
    }
#pragma unroll
    for (int j = 0; j < COUT / 2; j++)
        g_hh[n * (COUT / 2) + j] = __floats2half2_rn(hv[2 * j], hv[2 * j + 1]);
#pragma unroll
    for (int h = 0; h < H; h++) { g_als[n * H + h] = als[h]; g_ald[n * H + h] = ald[h]; }
}

// ---------------- launch ----------------
extern "C" void kernel_launch(void* const* d_in, const int* in_sizes, int n_in,
                              void* d_out, int out_size) {
    const float* x   = (const float*)d_in[0];
    const int*   ei  = (const int*)d_in[1];
    const float* W1  = (const float*)d_in[2];
    const float* as1 = (const float*)d_in[3];
    const float* ad1 = (const float*)d_in[4];
    const float* b1  = (const float*)d_in[5];
    const float* W2  = (const float*)d_in[6];
    const float* as2 = (const float*)d_in[7];
    const float* ad2 = (const float*)d_in[8];
    const float* b2  = (const float*)d_in[9];
    const float* W3  = (const float*)d_in[10];
    const float* as3 = (const float*)d_in[11];
    const float* ad3 = (const float*)d_in[12];
    const float* b3  = (const float*)d_in[13];
    const float* Wo  = (const float*)d_in[14];
    const float* bo  = (const float*)d_in[15];
    float* out = (float*)d_out;

    const int4* src4 = (const int4*)ei;            // edge_index[0]
    const int4* dst4 = (const int4*)(ei + NE);     // edge_index[1]

    // CSR build by dst (parallel 3-level scan; self-loops folded in)
    k_zero<<<(NN + 255) / 256, 256>>>();
    k_count<<<(NE / 4 + 255) / 256, 256>>>(dst4);
    k_blksum<<<NB, SCAN_BLK>>>();
    k_blkscan<<<1, 512>>>();
    k_offsets<<<NB, SCAN_BLK>>>();
    k_scatter<<<(NE / 4 + 255) / 256, 256>>>(src4, dst4);

    const int EB = NN / NW;   // 12500 blocks, one warp per dst node
    // layer 1 (H=2, C=16)
    k_node1<<<(NN + 255) / 256, 256>>>(x, W1, as1, ad1);
    k_edge2<<<EB, 256>>>();
    // layer 2 (H=2, C=16)
    k_mid<32, 32, 2><<<(NN + 255) / 256, 256>>>(b1, W2, as2, ad2);
    k_edge2<<<EB, 256>>>();
    // layer 3 (H=1, C=8) + fused output head
    k_mid<32, 8, 1><<<(NN + 255) / 256, 256>>>(b2, W3, as3, ad3);
    k_edge1_final<<<EB, 256>>>(b3, Wo, bo, out);

    (void)in_sizes; (void)n_in; (void)out_size;
}

// round 7
// speedup vs baseline: 1.4716x; 1.4716x over previous
#include <cuda_runtime.h>

#define NN 100000
#define NE 3200000
#define ET (NE + NN)
#define SMAX 128
#define NW 8            // warps per edge-kernel block
#define SCAN_BLK 256
#define NB ((NN + SCAN_BLK - 1) / SCAN_BLK)   // 391

// ---------------- scratch (device globals; no allocs allowed) ----------------
__device__ __align__(128) int   g_cnt[NN];        // counts (init 1 for self-loop), then cursor
__device__ __align__(128) int   g_off[NN + 1];    // CSR offsets by dst
__device__ __align__(128) int   g_csr[ET];        // src node id per CSR slot
__device__ __align__(128) int   g_blk[NB];        // per-block sums -> inclusive prefixes
__device__ __align__(128) float g_h[NN * 32];     // node features fp32 (stride = CH of layer)
__device__ __align__(128) float g_o[NN * 32];     // aggregated out (fp32)
__device__ __align__(128) float g_als[NN * 2];    // per-node src-attention scalar [n][h]
__device__ __align__(128) float g_ald[NN * 2];    // per-node dst-attention scalar [n][h]

// ---------------- CSR build ----------------
__global__ void k_zero() {
    int i = blockIdx.x * blockDim.x + threadIdx.x;
    if (i < NN) g_cnt[i] = 1;          // self-loop pre-counted
}

__global__ void k_count(const int4* __restrict__ dst4) {
    int e = blockIdx.x * blockDim.x + threadIdx.x;
    if (e >= NE / 4) return;
    int4 d = dst4[e];
    atomicAdd(&g_cnt[d.x], 1);
    atomicAdd(&g_cnt[d.y], 1);
    atomicAdd(&g_cnt[d.z], 1);
    atomicAdd(&g_cnt[d.w], 1);
}

// per-block sums of g_cnt
__global__ void k_blksum() {
    __shared__ int sm[SCAN_BLK];
    int n = blockIdx.x * SCAN_BLK + threadIdx.x;
    sm[threadIdx.x] = (n < NN) ? g_cnt[n] : 0;
    __syncthreads();
#pragma unroll
    for (int o = SCAN_BLK / 2; o > 0; o >>= 1) {
        if (threadIdx.x < o) sm[threadIdx.x] += sm[threadIdx.x + o];
        __syncthreads();
    }
    if (threadIdx.x == 0) g_blk[blockIdx.x] = sm[0];
}

// single small block: inclusive scan over the NB block sums
__global__ void k_blkscan() {
    __shared__ int sm[512];
    int tid = threadIdx.x;
    sm[tid] = (tid < NB) ? g_blk[tid] : 0;
    __syncthreads();
    for (int d = 1; d < 512; d <<= 1) {
        int t = (tid >= d) ? sm[tid - d] : 0;
        __syncthreads();
        sm[tid] += t;
        __syncthreads();
    }
    if (tid < NB) g_blk[tid] = sm[tid];   // inclusive prefix
}

// per-block: local scan of 256 counts, add block prefix, emit offsets + self-loop + cursor
__global__ void k_offsets() {
    __shared__ int sm[SCAN_BLK];
    int b = blockIdx.x;
    int n = b * SCAN_BLK + threadIdx.x;
    int c = (n < NN) ? g_cnt[n] : 0;
    sm[threadIdx.x] = c;
    __syncthreads();
    for (int d = 1; d < SCAN_BLK; d <<= 1) {
        int t = (threadIdx.x >= d) ? sm[threadIdx.x - d] : 0;
        __syncthreads();
        sm[threadIdx.x] += t;
        __syncthreads();
    }
    int blocksum = sm[SCAN_BLK - 1];
    int base = g_blk[b] - blocksum;               // exclusive block prefix
    int run = base + sm[threadIdx.x] - c;         // exclusive node prefix
    if (n < NN) {
        g_off[n] = run;
        g_csr[run] = n;          // self-loop first
        g_cnt[n] = run + 1;      // scatter cursor after self-loop
        if (n == NN - 1) g_off[NN] = run + c;
    }
}

__global__ void k_scatter(const int4* __restrict__ src4, const int4* __restrict__ dst4) {
    int e = blockIdx.x * blockDim.x + threadIdx.x;
    if (e >= NE / 4) return;
    int4 s = src4[e];
    int4 d = dst4[e];
    g_csr[atomicAdd(&g_cnt[d.x], 1)] = s.x;
    g_csr[atomicAdd(&g_cnt[d.y], 1)] = s.y;
    g_csr[atomicAdd(&g_cnt[d.z], 1)] = s.z;
    g_csr[atomicAdd(&g_cnt[d.w], 1)] = s.w;
}

// ---------------- layer 1 node transform ----------------
__global__ void k_node1(const float* __restrict__ x, const float* __restrict__ W,
                        const float* __restrict__ as_, const float* __restrict__ ad_) {
    int n = blockIdx.x * blockDim.x + threadIdx.x;
    if (n >= NN) return;
    float x0 = x[n * 3 + 0], x1 = x[n * 3 + 1], x2 = x[n * 3 + 2];
    float als0 = 0.f, als1 = 0.f, ald0 = 0.f, ald1 = 0.f;
    float hv[32];
#pragma unroll
    for (int c = 0; c < 32; c++) {
        float h = fmaf(x0, __ldg(&W[c]), fmaf(x1, __ldg(&W[32 + c]), x2 * __ldg(&W[64 + c])));
        hv[c] = h;
        float vs = h * __ldg(&as_[c]), vd = h * __ldg(&ad_[c]);
        if (c < 16) { als0 += vs; ald0 += vd; }
        else        { als1 += vs; ald1 += vd; }
    }
#pragma unroll
    for (int j = 0; j < 8; j++)
        ((float4*)g_h)[n * 8 + j] = make_float4(hv[4*j], hv[4*j+1], hv[4*j+2], hv[4*j+3]);
    g_als[n * 2 + 0] = als0; g_als[n * 2 + 1] = als1;
    g_ald[n * 2 + 0] = ald0; g_ald[n * 2 + 1] = ald1;
}

__device__ __forceinline__ float lrelu(float v) { return v > 0.f ? v : 0.2f * v; }

// ---------------- edge aggregation, H=2 CH=32: one warp per dst ----------------
__global__ void __launch_bounds__(256) k_edge2() {
    __shared__ int   s_s[NW][SMAX];
    __shared__ float s_a[NW][SMAX * 2];   // [jj][h] interleaved
    int widx = threadIdx.x >> 5;
    int lane = threadIdx.x & 31;
    int w = blockIdx.x * NW + widx;       // NN % NW == 0

    int start = g_off[w];
    int deg   = g_off[w + 1] - start;
    float2 aldv = ((const float2*)g_ald)[w];

    // phase A: exp(logit) per edge, denominator, cache (src, e0, e1)
    float ss0 = 0.f, ss1 = 0.f;
    for (int jj = lane; jj < deg; jj += 32) {
        int s = g_csr[start + jj];
        float2 av = ((const float2*)g_als)[s];
        float e0 = __expf(lrelu(av.x + aldv.x));
        float e1 = __expf(lrelu(av.y + aldv.y));
        ss0 += e0; ss1 += e1;
        if (jj < SMAX) {
            s_s[widx][jj] = s;
            ((float2*)s_a[widx])[jj] = make_float2(e0, e1);
        }
    }
#pragma unroll
    for (int o = 16; o > 0; o >>= 1) {
        ss0 += __shfl_xor_sync(0xffffffffu, ss0, o);
        ss1 += __shfl_xor_sync(0xffffffffu, ss1, o);
    }
    __syncwarp();

    // phase C: 4 edge groups x 8 float4 channel-quads; LDG.128 per edge-slice
    const float4* h4 = (const float4*)g_h;
    int eg = lane >> 3;        // edge group 0..3
    int c4 = lane & 7;         // float4 index -> channels 4c4..4c4+3
    int hsel = c4 >> 2;        // head of this quad
    float ax = 0.f, ay = 0.f, az = 0.f, aw = 0.f;
    int lim = min(deg, SMAX);
    int base = 0;
    for (; base + 8 <= lim; base += 8) {
        int e0 = base + eg, e1 = base + 4 + eg;
        int s0 = s_s[widx][e0], s1 = s_s[widx][e1];
        float a0 = s_a[widx][e0 * 2 + hsel];
        float a1 = s_a[widx][e1 * 2 + hsel];
        float4 f0 = h4[s0 * 8 + c4];
        float4 f1 = h4[s1 * 8 + c4];
        ax = fmaf(a0, f0.x, ax); ay = fmaf(a0, f0.y, ay);
        az = fmaf(a0, f0.z, az); aw = fmaf(a0, f0.w, aw);
        ax = fmaf(a1, f1.x, ax); ay = fmaf(a1, f1.y, ay);
        az = fmaf(a1, f1.z, az); aw = fmaf(a1, f1.w, aw);
    }
#pragma unroll 1
    for (int e = base + eg; e < lim; e += 4) {
        int s = s_s[widx][e];
        float a = s_a[widx][e * 2 + hsel];
        float4 f = h4[s * 8 + c4];
        ax = fmaf(a, f.x, ax); ay = fmaf(a, f.y, ay);
        az = fmaf(a, f.z, az); aw = fmaf(a, f.w, aw);
    }
#pragma unroll 1
    for (int e = lim + eg; e < deg; e += 4) {     // overflow fallback (deg > SMAX; ~never)
        int s = g_csr[start + e];
        float2 av = ((const float2*)g_als)[s];
        float v = (hsel ? av.y : av.x) + (hsel ? aldv.y : aldv.x);
        float a = __expf(lrelu(v));
        float4 f = h4[s * 8 + c4];
        ax = fmaf(a, f.x, ax); ay = fmaf(a, f.y, ay);
        az = fmaf(a, f.z, az); aw = fmaf(a, f.w, aw);
    }
    // reduce across the 4 edge groups (lane bits 3,4)
#pragma unroll
    for (int o = 8; o <= 16; o <<= 1) {
        ax += __shfl_xor_sync(0xffffffffu, ax, o);
        ay += __shfl_xor_sync(0xffffffffu, ay, o);
        az += __shfl_xor_sync(0xffffffffu, az, o);
        aw += __shfl_xor_sync(0xffffffffu, aw, o);
    }
    float inv = 1.f / ((hsel ? ss1 : ss0) + 1e-16f);
    if (eg == 0)
        ((float4*)g_o)[w * 8 + c4] = make_float4(ax * inv, ay * inv, az * inv, aw * inv);
}

// ---------------- layer 3 edges (H=1, CH=8) fused with output head ----------------
__global__ void __launch_bounds__(256) k_edge1_final(
        const float* __restrict__ b3, const float* __restrict__ Wo,
        const float* __restrict__ bo, float* __restrict__ out) {
    __shared__ int   s_s[NW][SMAX];
    __shared__ float s_a[NW][SMAX];
    int widx = threadIdx.x >> 5;
    int lane = threadIdx.x & 31;
    int w = blockIdx.x * NW + widx;

    int start = g_off[w];
    int deg   = g_off[w + 1] - start;
    float aldv = g_ald[w];

    float ss = 0.f;
    for (int jj = lane; jj < deg; jj += 32) {
        int s = g_csr[start + jj];
        float e = __expf(lrelu(g_als[s] + aldv));
        ss += e;
        if (jj < SMAX) { s_s[widx][jj] = s; s_a[widx][jj] = e; }
    }
#pragma unroll
    for (int o = 16; o > 0; o >>= 1) ss += __shfl_xor_sync(0xffffffffu, ss, o);
    __syncwarp();
    float inv = 1.f / (ss + 1e-16f);

    // phase C: 16 edge groups x 2 float4 channel-quads (CH=8 -> 2 x float4 per node)
    const float4* h4 = (const float4*)g_h;
    int eg = lane >> 1;        // 0..15
    int c4 = lane & 1;         // 0..1 -> channels 4c4..4c4+3
    float ax = 0.f, ay = 0.f, az = 0.f, aw = 0.f;
    int lim = min(deg, SMAX);
    for (int e = eg; e < lim; e += 16) {
        float a = s_a[widx][e];
        float4 f = h4[s_s[widx][e] * 2 + c4];
        ax = fmaf(a, f.x, ax); ay = fmaf(a, f.y, ay);
        az = fmaf(a, f.z, az); aw = fmaf(a, f.w, aw);
    }
#pragma unroll 1
    for (int e = lim + eg; e < deg; e += 16) {    // overflow fallback
        int s = g_csr[start + e];
        float a = __expf(lrelu(g_als[s] + aldv));
        float4 f = h4[s * 2 + c4];
        ax = fmaf(a, f.x, ax); ay = fmaf(a, f.y, ay);
        az = fmaf(a, f.z, az); aw = fmaf(a, f.w, aw);
    }
    // reduce over the 16 edge groups (lane bits 1..4)
#pragma unroll
    for (int o = 2; o <= 16; o <<= 1) {
        ax += __shfl_xor_sync(0xffffffffu, ax, o);
        ay += __shfl_xor_sync(0xffffffffu, ay, o);
        az += __shfl_xor_sync(0xffffffffu, az, o);
        aw += __shfl_xor_sync(0xffffffffu, aw, o);
    }

    // fused head on lanes 0 (ch 0-3) and 1 (ch 4-7): y = elu(out3+b3) @ Wo + bo
    float z0 = ax * inv + __ldg(&b3[4 * c4 + 0]);
    float z1 = ay * inv + __ldg(&b3[4 * c4 + 1]);
    float z2 = az * inv + __ldg(&b3[4 * c4 + 2]);
    float z3 = aw * inv + __ldg(&b3[4 * c4 + 3]);
    z0 = z0 > 0.f ? z0 : expm1f(z0);
    z1 = z1 > 0.f ? z1 : expm1f(z1);
    z2 = z2 > 0.f ? z2 : expm1f(z2);
    z3 = z3 > 0.f ? z3 : expm1f(z3);
    float p = fmaf(z0, __ldg(&Wo[4 * c4 + 0]),
             fmaf(z1, __ldg(&Wo[4 * c4 + 1]),
             fmaf(z2, __ldg(&Wo[4 * c4 + 2]), z3 * __ldg(&Wo[4 * c4 + 3]))));
    p += __shfl_xor_sync(0xffffffffu, p, 1);
    if (lane == 0) out[w] = p + __ldg(&bo[0]);
}

// ---------------- mid node transform ----------------
template <int CIN, int COUT, int H>
__global__ void k_mid(const float* __restrict__ b, const float* __restrict__ W,
                      const float* __restrict__ as_, const float* __restrict__ ad_) {
    __shared__ float sW[CIN * COUT];
    __shared__ float sb[CIN];
    __shared__ float sas[COUT], sad[COUT];
    for (int i = threadIdx.x; i < CIN * COUT; i += blockDim.x) sW[i] = W[i];
    for (int i = threadIdx.x; i < CIN; i += blockDim.x) sb[i] = b[i];
    for (int i = threadIdx.x; i < COUT; i += blockDim.x) { sas[i] = as_[i]; sad[i] = ad_[i]; }
    __syncthreads();

    int n = blockIdx.x * blockDim.x + threadIdx.x;
    if (n >= NN) return;
    float z[CIN];
#pragma unroll
    for (int i = 0; i < CIN; i++) {
        float v = g_o[n * CIN + i] + sb[i];
        z[i] = v > 0.f ? v : expm1f(v);              // elu
    }
    const int C = COUT / H;
    float als[H], ald[H];
#pragma unroll
    for (int h = 0; h < H; h++) { als[h] = 0.f; ald[h] = 0.f; }
    float hv[COUT];
#pragma unroll
    for (int c = 0; c < COUT; c++) {
        float acc = 0.f;
#pragma unroll
        for (int i = 0; i < CIN; i++) acc = fmaf(z[i], sW[i * COUT + c], acc);
        hv[c] = acc;
        int h = c / C;
        als[h] = fmaf(acc, sas[c], als[h]);
        ald[h] = fmaf(acc, sad[c], ald[h]);
    }
#pragma unroll
    for (int j = 0; j < COUT / 4; j++)
        ((float4*)g_h)[n * (COUT / 4) + j] =
            make_float4(hv[4*j], hv[4*j+1], hv[4*j+2], hv[4*j+3]);
#pragma unroll
    for (int h = 0; h < H; h++) { g_als[n * H + h] = als[h]; g_ald[n * H + h] = ald[h]; }
}

// ---------------- launch ----------------
extern "C" void kernel_launch(void* const* d_in, const int* in_sizes, int n_in,
                              void* d_out, int out_size) {
    const float* x   = (const float*)d_in[0];
    const int*   ei  = (const int*)d_in[1];
    const float* W1  = (const float*)d_in[2];
    const float* as1 = (const float*)d_in[3];
    const float* ad1 = (const float*)d_in[4];
    const float* b1  = (const float*)d_in[5];
    const float* W2  = (const float*)d_in[6];
    const float* as2 = (const float*)d_in[7];
    const float* ad2 = (const float*)d_in[8];
    const float* b2  = (const float*)d_in[9];
    const float* W3  = (const float*)d_in[10];
    const float* as3 = (const float*)d_in[11];
    const float* ad3 = (const float*)d_in[12];
    const float* b3  = (const float*)d_in[13];
    const float* Wo  = (const float*)d_in[14];
    const float* bo  = (const float*)d_in[15];
    float* out = (float*)d_out;

    const int4* src4 = (const int4*)ei;            // edge_index[0]
    const int4* dst4 = (const int4*)(ei + NE);     // edge_index[1]

    // CSR build by dst (parallel 3-level scan; self-loops folded in)
    k_zero<<<(NN + 255) / 256, 256>>>();
    k_count<<<(NE / 4 + 255) / 256, 256>>>(dst4);
    k_blksum<<<NB, SCAN_BLK>>>();
    k_blkscan<<<1, 512>>>();
    k_offsets<<<NB, SCAN_BLK>>>();
    k_scatter<<<(NE / 4 + 255) / 256, 256>>>(src4, dst4);

    const int EB = NN / NW;   // 12500 blocks, one warp per dst node
    // layer 1 (H=2, C=16)
    k_node1<<<(NN + 255) / 256, 256>>>(x, W1, as1, ad1);
    k_edge2<<<EB, 256>>>();
    // layer 2 (H=2, C=16)
    k_mid<32, 32, 2><<<(NN + 255) / 256, 256>>>(b1, W2, as2, ad2);
    k_edge2<<<EB, 256>>>();
    // layer 3 (H=1, C=8) + fused output head
    k_mid<32, 8, 1><<<(NN + 255) / 256, 256>>>(b2, W3, as3, ad3);
    k_edge1_final<<<EB, 256>>>(b3, Wo, bo, out);

    (void)in_sizes; (void)n_in; (void)out_size;
}